// round 17
// baseline (speedup 1.0000x reference)
#include <cuda_runtime.h>
#include <cuda_bf16.h>

#define T_LEN 500
#define QUADS 125            // T_LEN/4 float4 quads per row
#define S_SIMS 4096
#define D_DIM 6
#define A_DIM 3
#define H_DIM 64
#define JP    (H_DIM / 2)
#define JP_SPLIT 8
#define ALPHA_C 0.1f
#define BLOCK_THREADS 128
#define EPT 4

// constant layout (ulonglong2 entries)
#define OFF_WW 0
#define OFF_CC (JP * D_DIM)
#define OFF_BB (OFF_CC + JP * 2)
#define OFF_SC (OFF_BB + JP)
#define CALL_N (OFF_SC + 3)

__constant__ ulonglong2 cALL[CALL_N];
__device__   ulonglong2 g_stage[CALL_N];
__device__   float g_partial[S_SIMS];
__device__   int   g_count = 0;

// ---- packed f32x2 helpers ----
__device__ __forceinline__ unsigned long long pk2(float a, float b) {
    unsigned long long r;
    asm("mov.b64 %0, {%1, %2};" : "=l"(r) : "f"(a), "f"(b));
    return r;
}
__device__ __forceinline__ void upk2(unsigned long long v, float& a, float& b) {
    asm("mov.b64 {%0, %1}, %2;" : "=f"(a), "=f"(b) : "l"(v));
}
__device__ __forceinline__ unsigned long long fma2(unsigned long long a,
                                                   unsigned long long b,
                                                   unsigned long long c) {
    unsigned long long d;
    asm("fma.rn.f32x2 %0, %1, %2, %3;" : "=l"(d) : "l"(a), "l"(b), "l"(c));
    return d;
}
__device__ __forceinline__ unsigned long long relu2(unsigned long long v) {
    float a, b;
    upk2(v, a, b);
    return pk2(fmaxf(a, 0.0f), fmaxf(b, 0.0f));
}

// ---- one jp step of the fused MLP hot loop ----
__device__ __forceinline__ void jp_step(int jp, const unsigned long long x2[EPT][D_DIM],
                                        unsigned long long* m0a, unsigned long long* m1a,
                                        unsigned long long* m2a, unsigned long long* bla) {
    const ulonglong2* wrow = &cALL[OFF_WW + jp * D_DIM];
    const ulonglong2 bi = cALL[OFF_BB + jp];

    unsigned long long hp[EPT], hb[EPT];
#pragma unroll
    for (int k = 0; k < EPT; k++) { hp[k] = bi.x; hb[k] = bi.y; }
#pragma unroll
    for (int d = 0; d < D_DIM; d++) {
        const ulonglong2 w = wrow[d];
#pragma unroll
        for (int k = 0; k < EPT; k++) {
            hp[k] = fma2(x2[k][d], w.x, hp[k]);
            hb[k] = fma2(x2[k][d], w.y, hb[k]);
        }
    }
    const ulonglong2 cA = cALL[OFF_CC + 2 * jp + 0];
    const ulonglong2 cB = cALL[OFF_CC + 2 * jp + 1];
#pragma unroll
    for (int k = 0; k < EPT; k++) {
        hp[k] = relu2(hp[k]);
        hb[k] = relu2(hb[k]);
        m0a[k] = fma2(hp[k], cA.x, m0a[k]);
        m1a[k] = fma2(hp[k], cA.y, m1a[k]);
        m2a[k] = fma2(hp[k], cB.x, m2a[k]);
        bla[k] = fma2(hb[k], cB.y, bla[k]);
    }
}

// ---- one-block repack: pair-pack weights + Cholesky into staging ----
__global__ void mepg_pack(const float* __restrict__ pW1, const float* __restrict__ pb1,
                          const float* __restrict__ pW2, const float* __restrict__ pb2,
                          const float* __restrict__ bW1, const float* __restrict__ bb1,
                          const float* __restrict__ bW2, const float* __restrict__ bb2,
                          const float* __restrict__ sd) {
    const int jp = threadIdx.x;
    if (jp < JP) {
        const int j0 = 2 * jp, j1 = j0 + 1;
#pragma unroll
        for (int d = 0; d < D_DIM; d++) {
            g_stage[OFF_WW + jp * D_DIM + d].x = pk2(pW1[j0 * D_DIM + d], pW1[j1 * D_DIM + d]);
            g_stage[OFF_WW + jp * D_DIM + d].y = pk2(bW1[j0 * D_DIM + d], bW1[j1 * D_DIM + d]);
        }
        g_stage[OFF_CC + 2 * jp + 0].x = pk2(pW2[0 * H_DIM + j0], pW2[0 * H_DIM + j1]);
        g_stage[OFF_CC + 2 * jp + 0].y = pk2(pW2[1 * H_DIM + j0], pW2[1 * H_DIM + j1]);
        g_stage[OFF_CC + 2 * jp + 1].x = pk2(pW2[2 * H_DIM + j0], pW2[2 * H_DIM + j1]);
        g_stage[OFF_CC + 2 * jp + 1].y = pk2(bW2[j0], bW2[j1]);
        g_stage[OFF_BB + jp].x = pk2(pb1[j0], pb1[j1]);
        g_stage[OFF_BB + jp].y = pk2(bb1[j0], bb1[j1]);
    }
    if (jp == 0) {
        const float L00 = sqrtf(sd[0]);
        const float L10 = sd[3] / L00;
        const float L11 = sqrtf(sd[4] - L10 * L10);
        const float L20 = sd[6] / L00;
        const float L21 = (sd[7] - L20 * L10) / L11;
        const float L22 = sqrtf(sd[8] - L20 * L20 - L21 * L21);
        const float Li00 = 1.0f / L00;
        const float Li11 = 1.0f / L11;
        const float Li22 = 1.0f / L22;
        const float Li10 = -L10 * Li00 * Li11;
        const float Li21 = -L21 * Li11 * Li22;
        const float Li20 = (L10 * L21 - L20 * L11) * (Li00 * Li11 * Li22);
        const float cterm = -(logf(L00) + logf(L11) + logf(L22))
                            - 0.5f * 3.0f * 1.8378770664093453f;
        g_stage[OFF_SC + 0].x = pk2(pb2[0], pb2[1]);
        g_stage[OFF_SC + 0].y = pk2(pb2[2], bb2[0]);
        g_stage[OFF_SC + 1].x = pk2(Li00, Li10);
        g_stage[OFF_SC + 1].y = pk2(Li11, Li20);
        g_stage[OFF_SC + 2].x = pk2(Li21, Li22);
        g_stage[OFF_SC + 2].y = pk2(cterm, 0.0f);
    }
}

__global__ __launch_bounds__(BLOCK_THREADS, 6) void mepg_main(
    const float* __restrict__ st,   // [S, D, T]
    const float* __restrict__ at,   // [S, A, T]
    const float* __restrict__ rw,   // [S, T]
    float* __restrict__ out)
{
    __shared__ float sRedA[BLOCK_THREADS / 32];
    __shared__ float sRedB[BLOCK_THREADS / 32];
    __shared__ int   sIsLast;

    const int tid = threadIdx.x;
    const int s   = blockIdx.x;

    const float4* st4 = reinterpret_cast<const float4*>(st + (size_t)s * D_DIM * T_LEN);
    const float4* at4 = reinterpret_cast<const float4*>(at + (size_t)s * A_DIM * T_LEN);
    const float4* rw4 = reinterpret_cast<const float4*>(rw + (size_t)s * T_LEN);

    // thread owns 4 consecutive t: t = tid*4 + k; valid iff tid < 125 (uniform)
    const bool vld = (tid < QUADS);
    const int  q   = vld ? tid : 0;

    // ---- front batch: ONLY 6 state LDG.128 (MLP_p1 = 6) ----
    unsigned long long x2[EPT][D_DIM];
#pragma unroll
    for (int d = 0; d < D_DIM; d++) {
        const float4 v = st4[d * QUADS + q];
        x2[0][d] = pk2(v.x, v.x);
        x2[1][d] = pk2(v.y, v.y);
        x2[2][d] = pk2(v.z, v.z);
        x2[3][d] = pk2(v.w, v.w);
    }

    // ---- scalars from constant ----
    float pb20, pb21, pb22, bb20;
    upk2(cALL[OFF_SC + 0].x, pb20, pb21);
    upk2(cALL[OFF_SC + 0].y, pb22, bb20);
    float Li00, Li10, Li11, Li20, Li21, Li22, cterm, dummy;
    upk2(cALL[OFF_SC + 1].x, Li00, Li10);
    upk2(cALL[OFF_SC + 1].y, Li11, Li20);
    upk2(cALL[OFF_SC + 2].x, Li21, Li22);
    upk2(cALL[OFF_SC + 2].y, cterm, dummy);

    unsigned long long m0a[EPT], m1a[EPT], m2a[EPT], bla[EPT];
#pragma unroll
    for (int k = 0; k < EPT; k++) {
        m0a[k] = pk2(pb20, 0.0f);
        m1a[k] = pk2(pb21, 0.0f);
        m2a[k] = pk2(pb22, 0.0f);
        bla[k] = pk2(bb20, 0.0f);
    }

    // ---- hot loop part 1 ----
#pragma unroll
    for (int jp = 0; jp < JP_SPLIT; jp++)
        jp_step(jp, x2, m0a, m1a, m2a, bla);

    // ---- mid-loop: 4 action/reward LDG.128; latency hides under part 2 ----
    float4 aT[A_DIM], rT;
#pragma unroll
    for (int i = 0; i < A_DIM; i++) aT[i] = at4[i * QUADS + q];
    rT = rw4[q];

    // ---- hot loop part 2 ----
#pragma unroll
    for (int jp = JP_SPLIT; jp < JP; jp++)
        jp_step(jp, x2, m0a, m1a, m2a, bla);

    // ---- tail: uniform validity; ll + per-s streaming sums ----
    float SA = 0.0f, SL = 0.0f;
    if (vld) {
        const float a0v[4] = {aT[0].x, aT[0].y, aT[0].z, aT[0].w};
        const float a1v[4] = {aT[1].x, aT[1].y, aT[1].z, aT[1].w};
        const float a2v[4] = {aT[2].x, aT[2].y, aT[2].z, aT[2].w};
        const float rv4[4] = {rT.x, rT.y, rT.z, rT.w};
#pragma unroll
        for (int k = 0; k < EPT; k++) {
            const int t = tid * 4 + k;
            float lo, hi;
            upk2(m0a[k], lo, hi); const float m0 = lo + hi;
            upk2(m1a[k], lo, hi); const float m1 = lo + hi;
            upk2(m2a[k], lo, hi); const float m2 = lo + hi;
            upk2(bla[k], lo, hi); const float bl = lo + hi;
            const float d0 = a0v[k] - m0;
            const float d1 = a1v[k] - m1;
            const float d2 = a2v[k] - m2;
            const float z0 = Li00 * d0;
            const float z1 = fmaf(Li10, d0, Li11 * d1);
            const float z2 = fmaf(Li20, d0, fmaf(Li21, d1, Li22 * d2));
            const float ll = fmaf(-0.5f, fmaf(z0, z0, fmaf(z1, z1, z2 * z2)), cterm);
            const float gg = __expf(rv4[k]) - ALPHA_C * ll;
            SA = fmaf((float)(t + 1), gg, SA) - bl;
            SL += ll;
        }
    }

    // ---- block reduction ----
    const int lane = tid & 31;
    const int warp = tid >> 5;
#pragma unroll
    for (int o = 16; o > 0; o >>= 1) {
        SA += __shfl_down_sync(0xffffffffu, SA, o);
        SL += __shfl_down_sync(0xffffffffu, SL, o);
    }
    if (lane == 0) { sRedA[warp] = SA; sRedB[warp] = SL; }
    __syncthreads();
    if (tid == 0) {
        float a = 0.0f, b = 0.0f;
#pragma unroll
        for (int w = 0; w < BLOCK_THREADS / 32; w++) { a += sRedA[w]; b += sRedB[w]; }
        g_partial[s] = a * b;
        __threadfence();
        const int c = atomicAdd(&g_count, 1);
        sIsLast = (c == gridDim.x - 1) ? 1 : 0;
    }
    __syncthreads();

    // ---- last block folds final reduction (deterministic order) ----
    if (sIsLast) {
        float v = 0.0f;
        for (int i = tid; i < S_SIMS; i += BLOCK_THREADS) v += __ldcg(&g_partial[i]);
#pragma unroll
        for (int o = 16; o > 0; o >>= 1) v += __shfl_down_sync(0xffffffffu, v, o);
        if (lane == 0) sRedA[warp] = v;
        __syncthreads();
        if (tid == 0) {
            float tot = 0.0f;
#pragma unroll
            for (int w = 0; w < BLOCK_THREADS / 32; w++) tot += sRedA[w];
            out[0] = tot * (1.0f / ((float)T_LEN * (float)S_SIMS));
            g_count = 0;   // reset for next graph replay
        }
    }
}

extern "C" void kernel_launch(void* const* d_in, const int* in_sizes, int n_in,
                              void* d_out, int out_size) {
    const float* st  = (const float*)d_in[0];
    const float* at  = (const float*)d_in[1];
    const float* rw  = (const float*)d_in[2];
    const float* pW1 = (const float*)d_in[3];
    const float* pb1 = (const float*)d_in[4];
    const float* pW2 = (const float*)d_in[5];
    const float* pb2 = (const float*)d_in[6];
    const float* bW1 = (const float*)d_in[7];
    const float* bb1 = (const float*)d_in[8];
    const float* bW2 = (const float*)d_in[9];
    const float* bb2 = (const float*)d_in[10];
    const float* sd  = (const float*)d_in[11];
    float* out = (float*)d_out;

    mepg_pack<<<1, 64>>>(pW1, pb1, pW2, pb2, bW1, bb1, bW2, bb2, sd);

    void* stage_ptr = nullptr;
    cudaGetSymbolAddress(&stage_ptr, g_stage);
    cudaMemcpyToSymbolAsync(cALL, stage_ptr, sizeof(ulonglong2) * CALL_N, 0,
                            cudaMemcpyDeviceToDevice, 0);

    mepg_main<<<S_SIMS, BLOCK_THREADS>>>(st, at, rw, out);
}